// round 11
// baseline (speedup 1.0000x reference)
#include <cuda_runtime.h>
#include <cuda_bf16.h>

// RepeatLayers: variable-length repeat_interleave along axis 0.
//   encoder_h: [N=8192, D=1024] fp32
//   repeats:   [N] int32 in [0, 8)
//   out:       [sum(repeats), D] fp32
//
// R11 = R8 structure scaled to ROWS_PER_CTA=16 (grid 512): halves the
// redundant per-CTA prefix-read traffic again (16.7MB -> 8.4MB). Rows are
// processed in 4 groups of 4, software-pipelined (load two groups ahead of
// stores) to bound live registers while keeping MLP up. Plain float4
// loads/stores (L2 policy hints measured neutral; dropped).

#define N_ROWS 8192
#define D_ELEMS 1024
#define D_VEC4 (D_ELEMS / 4)     // 256 float4 per row
#define ROWS_PER_CTA 16
#define NB_CTAS (N_ROWS / ROWS_PER_CTA)   // 512

__global__ __launch_bounds__(256, 4)
void repeat_fused_kernel(const float* __restrict__ src,
                         const int* __restrict__ repeats,
                         float* __restrict__ out) {
    const int t = threadIdx.x;                    // 0..255
    const int lane = t & 31;
    const int wid = t >> 5;
    const int row0 = blockIdx.x * ROWS_PER_CTA;   // first of this CTA's 16 rows

    // --- This CTA's 16 repeat counts (four int4) ---
    int rep[ROWS_PER_CTA];
#pragma unroll
    for (int q = 0; q < 4; q++) {
        int4 r4 = __ldg(reinterpret_cast<const int4*>(&repeats[row0 + 4 * q]));
        rep[4 * q + 0] = r4.x; rep[4 * q + 1] = r4.y;
        rep[4 * q + 2] = r4.z; rep[4 * q + 3] = r4.w;
    }

    const float4* srcv = reinterpret_cast<const float4*>(src);

    // --- Front-batch loads for groups 0 and 1 (rows 0..7) ---
    float4 v0[4], v1[4];
#pragma unroll
    for (int i = 0; i < 4; i++) {
        if (rep[i] > 0)     v0[i] = __ldg(srcv + (size_t)(row0 + i) * D_VEC4 + t);
    }
#pragma unroll
    for (int i = 0; i < 4; i++) {
        if (rep[4 + i] > 0) v1[i] = __ldg(srcv + (size_t)(row0 + 4 + i) * D_VEC4 + t);
    }

    // --- Cooperative prefix sum: off0 = sum(repeats[0..row0)) ---
    const int n4 = row0 >> 2;       // 4*blockIdx.x int4 words
    const int4* rp = reinterpret_cast<const int4*>(repeats);
    int sum = 0;
    for (int i = t; i < n4; i += 256) {
        int4 a = __ldg(&rp[i]);
        sum += a.x + a.y + a.z + a.w;
    }
#pragma unroll
    for (int d = 16; d >= 1; d >>= 1) {
        sum += __shfl_xor_sync(0xFFFFFFFFu, sum, d);
    }

    __shared__ int wsum[8];
    if (lane == 0) wsum[wid] = sum;
    __syncthreads();
    if (wid == 0) {   // full warp active
        int s2 = (lane < 8) ? wsum[lane] : 0;
#pragma unroll
        for (int d = 16; d >= 1; d >>= 1) {
            s2 += __shfl_xor_sync(0xFFFFFFFFu, s2, d);
        }
        if (lane == 0) wsum[0] = s2;
    }
    __syncthreads();

    // Per-row output offsets (exclusive).
    int off[ROWS_PER_CTA];
    off[0] = wsum[0];
#pragma unroll
    for (int i = 1; i < ROWS_PER_CTA; i++) off[i] = off[i - 1] + rep[i - 1];

    float4* outv = reinterpret_cast<float4*>(out);

    // --- Pipelined: store G0 / load G2, store G1 / load G3, store G2, G3 ---
    float4 v2[4], v3[4];

#pragma unroll
    for (int i = 0; i < 4; i++) {
        if (rep[8 + i] > 0) v2[i] = __ldg(srcv + (size_t)(row0 + 8 + i) * D_VEC4 + t);
    }
#pragma unroll
    for (int i = 0; i < 4; i++) {
        float4* o = outv + (size_t)off[i] * D_VEC4 + t;
#pragma unroll 8
        for (int r = 0; r < rep[i]; r++) { *o = v0[i]; o += D_VEC4; }
    }

#pragma unroll
    for (int i = 0; i < 4; i++) {
        if (rep[12 + i] > 0) v3[i] = __ldg(srcv + (size_t)(row0 + 12 + i) * D_VEC4 + t);
    }
#pragma unroll
    for (int i = 0; i < 4; i++) {
        float4* o = outv + (size_t)off[4 + i] * D_VEC4 + t;
#pragma unroll 8
        for (int r = 0; r < rep[4 + i]; r++) { *o = v1[i]; o += D_VEC4; }
    }

#pragma unroll
    for (int i = 0; i < 4; i++) {
        float4* o = outv + (size_t)off[8 + i] * D_VEC4 + t;
#pragma unroll 8
        for (int r = 0; r < rep[8 + i]; r++) { *o = v2[i]; o += D_VEC4; }
    }

#pragma unroll
    for (int i = 0; i < 4; i++) {
        float4* o = outv + (size_t)off[12 + i] * D_VEC4 + t;
#pragma unroll 8
        for (int r = 0; r < rep[12 + i]; r++) { *o = v3[i]; o += D_VEC4; }
    }
}

extern "C" void kernel_launch(void* const* d_in, const int* in_sizes, int n_in,
                              void* d_out, int out_size) {
    const float* encoder_h;
    const int* repeats;
    if (in_sizes[0] == N_ROWS * D_ELEMS) {
        encoder_h = (const float*)d_in[0];
        repeats   = (const int*)d_in[1];
    } else {
        encoder_h = (const float*)d_in[1];
        repeats   = (const int*)d_in[0];
    }
    float* out = (float*)d_out;
    (void)n_in; (void)out_size;

    repeat_fused_kernel<<<NB_CTAS, 256>>>(encoder_h, repeats, out);
}